// round 9
// baseline (speedup 1.0000x reference)
#include <cuda_runtime.h>
#include <cuda_fp16.h>
#include <cstdint>

#define NB    32
#define CIN   128
#define COUT  128
#define INH   64
#define INW   64
#define OUTHW 16384   // 128*128

// ---------------- scratch (device globals: allocation-free) ----------------
__device__ __half g_bext[(size_t)4 * COUT * 512];        // [par][co][k] fp16(W)

// ---------------- helpers ----------------
__device__ __forceinline__ uint32_t smem_u32(const void* p) {
    uint32_t a;
    asm("{ .reg .u64 t; cvta.to.shared.u64 t, %1; cvt.u32.u64 %0, t; }" : "=r"(a) : "l"(p));
    return a;
}
__device__ __forceinline__ void cp_async16(uint32_t dst, const void* src, uint32_t sz) {
    asm volatile("cp.async.cg.shared.global [%0], [%1], 16, %2;"
                 :: "r"(dst), "l"(src), "r"(sz) : "memory");
}
#define CP_COMMIT() asm volatile("cp.async.commit_group;" ::: "memory")
#define CP_WAIT(n)  asm volatile("cp.async.wait_group %0;" :: "n"(n) : "memory")

__device__ __forceinline__ void ldsm_x4(uint32_t* r, uint32_t addr) {
    asm volatile("ldmatrix.sync.aligned.m8n8.x4.shared.b16 {%0,%1,%2,%3}, [%4];"
                 : "=r"(r[0]), "=r"(r[1]), "=r"(r[2]), "=r"(r[3]) : "r"(addr));
}
__device__ __forceinline__ void mma_fp16(float* c, const uint32_t* a, const uint32_t* b) {
    asm volatile(
        "mma.sync.aligned.m16n8k16.row.col.f32.f16.f16.f32 "
        "{%0,%1,%2,%3}, {%4,%5,%6,%7}, {%8,%9}, {%0,%1,%2,%3};"
        : "+f"(c[0]), "+f"(c[1]), "+f"(c[2]), "+f"(c[3])
        : "r"(a[0]), "r"(a[1]), "r"(a[2]), "r"(a[3]), "r"(b[0]), "r"(b[1]));
}

// =================== kernel 1: B_ext [par][co][k=512] = fp16(W) ===================
// k = t*128 + ci ; tap t = (dh,dw), kernel coords kh = ph+2dh, kw = pw+2dw.
__global__ __launch_bounds__(256) void build_bext_kernel(const float* __restrict__ W) {
    const int idx = blockIdx.x * 256 + threadIdx.x;   // < 262144
    const int k = idx & 511;
    const int rco = idx >> 9;
    const int co = rco & 127, par = rco >> 7;
    const int t = k >> 7, ci = k & 127;
    const int dh = t >> 1, dw = t & 1, ph = par >> 1, pw = par & 1;
    const int kh = ph + 2 * dh, kw = pw + 2 * dw;
    g_bext[idx] = __float2half_rn(W[(((size_t)(kh * 4 + kw)) * CIN + ci) * COUT + co]);
}

// =================== kernel 2: fused convert + mma.sync GEMM ===================
// Block = (parity, n, itile). M=128 (2 i-rows x 64 j), N=128 co, K'=512, 8 chunks of 64.
// A: block converts its own x-slice (3 ih x 66 iw halo x 128 ci, fp32 NCHW -> fp16)
//    into an SMEM stage once; ldmatrix reads A directly from it each chunk.
//    Stage row R = ih_s*66 + iwst (iwst = global_iw + 1), 256 B/row (128 ci fp16),
//    16B-chunk swizzle: chunk ^ (R & 7). OOB halo rows stored as zeros.
// B: 3-stage cp.async pipeline (16 KB/stage), ONE barrier per chunk.
// 4 warps (128 thr), 2x2 grid of 64x64 warp tiles: 4(mt) x 8(nt) m16n8k16 each.
__global__ __launch_bounds__(128, 2) void tconv_gemm(const float* __restrict__ x,
                                                     const float* __restrict__ bias,
                                                     float* __restrict__ out) {
    extern __shared__ char dynsmem[];
    const uint32_t astage = (smem_u32(dynsmem) + 1023u) & ~1023u;  // 198*256 = 50688 B
    const uint32_t btiles = astage + 51200u;                       // 3 x 16384 B

    const int tid = threadIdx.x, wid = tid >> 5, lane = tid & 31;
    const int blk = blockIdx.x;
    const int par = blk & 3, rest = blk >> 2;
    const int itile = rest & 31, n = rest >> 5;
    const int ph = par >> 1, pw = par & 1;
    const int warp_m = wid >> 1, warp_n = wid & 1;    // 2x2, 64x64 per warp

    float acc[4][8][4];
#pragma unroll
    for (int mt = 0; mt < 4; ++mt)
#pragma unroll
        for (int nt = 0; nt < 8; ++nt)
#pragma unroll
            for (int q = 0; q < 4; ++q) acc[mt][nt][q] = 0.f;

    // ---- B tile issue for chunk c into stage c%3 ----
    auto issueB = [&](int c) {
        const uint32_t bbase = btiles + (uint32_t)(c % 3) * 16384u;
        const int kb = c * 64;
#pragma unroll
        for (int e = 0; e < 8; ++e) {
            const int idx = e * 128 + tid;            // 0..1023
            const int row = idx >> 3, s16 = idx & 7;
            uint32_t so = (uint32_t)(row * 128 + s16 * 16);
            so ^= (so >> 3) & 0x70;                   // SW128 swizzle
            const __half* src =
                g_bext + ((size_t)(par * COUT + row)) * 512 + kb + s16 * 8;
            cp_async16(bbase + so, src, 16u);
        }
        CP_COMMIT();
    };

    issueB(0);
    issueB(1);

    // ---- A-stage fill: convert this block's x slice fp32 NCHW -> fp16 stage ----
    {
        const int ih_base = itile * 2 + ph - 1;
        for (int p = wid; p < 384; p += 4) {          // p = ih_s*128 + ci
            const int ih_s = p >> 7, ci = p & 127;
            const int ihx = ih_base + ih_s;
            const bool rowok = (unsigned)ihx < 64u;
            const float* xrow = x + (((size_t)n * CIN + ci) * INH + ihx) * INW;
            const uint32_t cbyte = ((uint32_t)ci & 7u) * 2u;
            const uint32_t cchunk = (uint32_t)ci >> 3;
#pragma unroll
            for (int q = 0; q < 3; ++q) {
                const int iwst = lane + q * 32;
                if (iwst < 66) {
                    const int iwx = iwst - 1;
                    float v = (rowok && (unsigned)iwx < 64u) ? __ldg(xrow + iwx) : 0.f;
                    const uint32_t R = (uint32_t)(ih_s * 66 + iwst);
                    const uint32_t addr = astage + R * 256u
                                        + ((cchunk ^ (R & 7u)) << 4) + cbyte;
                    const unsigned short hv = __half_as_ushort(__float2half_rn(v));
                    asm volatile("st.shared.b16 [%0], %1;" :: "r"(addr), "h"(hv) : "memory");
                }
            }
        }
    }
    __syncthreads();   // A-stage complete before any compute

    // ---- compute chunk c: A from stage, B from stage c%3 ----
    auto compute = [&](int c) {
        const int t = c >> 1, h = c & 1;
        const int dh = t >> 1, dw = t & 1;
        const uint32_t bbase = btiles + (uint32_t)(c % 3) * 16384u;
        const int jlane = lane & 15;
        const uint32_t Rb = (uint32_t)((warp_m + dh) * 66 + jlane + dw + pw);
        const int achunk0 = h * 8 + (lane >> 4);      // + 2*s
        const int bmtx = lane >> 3, brlo = lane & 7;
        const int brow0 = warp_n * 64 + ((bmtx >> 1) << 3) + brlo;   // + q*16
        const int bcp0 = bmtx & 1;                    // + 2*s
#pragma unroll
        for (int s = 0; s < 4; ++s) {
            uint32_t a[4][4];
#pragma unroll
            for (int mt = 0; mt < 4; ++mt) {
                const uint32_t R = Rb + (uint32_t)(mt * 16);
                const uint32_t chunk = (uint32_t)(achunk0 + 2 * s) ^ (R & 7u);
                ldsm_x4(a[mt], astage + R * 256u + (chunk << 4));
            }
            uint32_t b[4][4];                         // q -> {b0n0,b1n0,b0n1,b1n1}
#pragma unroll
            for (int q = 0; q < 4; ++q) {
                const int r = brow0 + q * 16;
                const uint32_t chunk = (uint32_t)((bcp0 + 2 * s) ^ (r & 7));
                ldsm_x4(b[q], bbase + (uint32_t)r * 128u + chunk * 16u);
            }
#pragma unroll
            for (int mt = 0; mt < 4; ++mt)
#pragma unroll
                for (int nt = 0; nt < 8; ++nt)
                    mma_fp16(acc[mt][nt], a[mt], &b[nt >> 1][(nt & 1) * 2]);
        }
    };

#pragma unroll 1
    for (int c = 0; c < 8; ++c) {
        if (c < 7) { CP_WAIT(1); } else { CP_WAIT(0); }
        __syncthreads();
        compute(c);
        if (c + 2 < 8) issueB(c + 2);
    }

    // ---- epilogue: registers -> gmem ----
    // acc reg q: q0:(g, 2t) q1:(g, 2t+1) q2:(g+8, 2t) q3:(g+8, 2t+1)
    const int g = lane >> 2, tg = lane & 3;
    const int oh0 = 2 * (itile * 2 + warp_m) + ph;    // i_loc == warp_m for all rows
    float* const ob = out + (size_t)n * COUT * OUTHW + (size_t)oh0 * 128 + pw;
#pragma unroll
    for (int nt = 0; nt < 8; ++nt) {
        const int co = warp_n * 64 + nt * 8 + 2 * tg;
        const float b0 = __ldg(&bias[co]), b1 = __ldg(&bias[co + 1]);
        float* const oc0 = ob + (size_t)co * OUTHW;
        float* const oc1 = oc0 + OUTHW;
#pragma unroll
        for (int mt = 0; mt < 4; ++mt) {
            const int j0 = mt * 16 + g;               // j of rows (g) ; j0+8 for g+8
            oc0[2 * j0]        = acc[mt][nt][0] + b0;
            oc1[2 * j0]        = acc[mt][nt][1] + b1;
            oc0[2 * (j0 + 8)]  = acc[mt][nt][2] + b0;
            oc1[2 * (j0 + 8)]  = acc[mt][nt][3] + b1;
        }
    }
}

// =================== launch ===================
extern "C" void kernel_launch(void* const* d_in, const int* in_sizes, int n_in,
                              void* d_out, int out_size) {
    const float* x = (const float*)d_in[0];
    const float* W = (const float*)d_in[1];
    const float* b = (const float*)d_in[2];
    float* out = (float*)d_out;

    const int SMEM_DYN = 51200 + 3 * 16384 + 1024;   // A-stage + 3 B-stages + align
    cudaFuncSetAttribute(tconv_gemm, cudaFuncAttributeMaxDynamicSharedMemorySize, SMEM_DYN);

    build_bext_kernel<<<1024, 256>>>(W);             // 262144 threads
    tconv_gemm<<<4096, 128, SMEM_DYN>>>(x, b, out);  // (n*32+itile)*4 + parity
}

// round 10
// speedup vs baseline: 2.7418x; 2.7418x over previous
#include <cuda_runtime.h>
#include <cuda_fp16.h>
#include <cstdint>

#define NB    32
#define CIN   128
#define COUT  128
#define INH   64
#define INW   64
#define OUTHW 16384   // 128*128

// ---------------- scratch (device globals: allocation-free) ----------------
__device__ __half g_xh[(size_t)NB * INH * INW * CIN];    // NHWC  fp16(x)
__device__ __half g_bext[(size_t)4 * COUT * 512];        // [par][co][k] fp16(W)

// ---------------- helpers ----------------
__device__ __forceinline__ uint32_t smem_u32(const void* p) {
    uint32_t a;
    asm("{ .reg .u64 t; cvta.to.shared.u64 t, %1; cvt.u32.u64 %0, t; }" : "=r"(a) : "l"(p));
    return a;
}
__device__ __forceinline__ void cp_async16(uint32_t dst, const void* src, uint32_t sz) {
    asm volatile("cp.async.cg.shared.global [%0], [%1], 16, %2;"
                 :: "r"(dst), "l"(src), "r"(sz) : "memory");
}
#define CP_COMMIT() asm volatile("cp.async.commit_group;" ::: "memory")
#define CP_WAIT(n)  asm volatile("cp.async.wait_group %0;" :: "n"(n) : "memory")

__device__ __forceinline__ void ldsm_x4(uint32_t* r, uint32_t addr) {
    asm volatile("ldmatrix.sync.aligned.m8n8.x4.shared.b16 {%0,%1,%2,%3}, [%4];"
                 : "=r"(r[0]), "=r"(r[1]), "=r"(r[2]), "=r"(r[3]) : "r"(addr));
}
__device__ __forceinline__ void mma_fp16(float* c, const uint32_t* a, const uint32_t* b) {
    asm volatile(
        "mma.sync.aligned.m16n8k16.row.col.f32.f16.f16.f32 "
        "{%0,%1,%2,%3}, {%4,%5,%6,%7}, {%8,%9}, {%0,%1,%2,%3};"
        : "+f"(c[0]), "+f"(c[1]), "+f"(c[2]), "+f"(c[3])
        : "r"(a[0]), "r"(a[1]), "r"(a[2]), "r"(a[3]), "r"(b[0]), "r"(b[1]));
}

// =================== kernel 1: merged prologue ===================
// Blocks [0,2048): x fp32 NCHW -> fp16 NHWC (one (n, ih) slice per block).
// Blocks [2048,2176): B_ext [par][co][k=512] = fp16(W); k = t*128 + ci,
//   tap t=(dh,dw), kernel coords kh=ph+2dh, kw=pw+2dw.
__global__ __launch_bounds__(256) void prologue_kernel(const float* __restrict__ x,
                                                       const float* __restrict__ W) {
    const int bid = blockIdx.x;
    const int tid = threadIdx.x;

    if (bid < 2048) {
        __shared__ float tile[128][65];
        const int n = bid >> 6, ihh = bid & 63;

        // Phase 1: 2048 float4 loads (8 per thread), LDG.128 coalesced.
        const float* xb = x + ((size_t)n * CIN * INH + ihh) * INW;
#pragma unroll
        for (int e = 0; e < 8; ++e) {
            int flat = e * 256 + tid;          // < 2048
            int ci = flat >> 4, iw4 = flat & 15;
            float4 v = __ldg((const float4*)(xb + (size_t)ci * INH * INW) + iw4);
            tile[ci][iw4 * 4 + 0] = v.x;
            tile[ci][iw4 * 4 + 1] = v.y;
            tile[ci][iw4 * 4 + 2] = v.z;
            tile[ci][iw4 * 4 + 3] = v.w;
        }
        __syncthreads();

        // Phase 2: transpose to NHWC half2, coalesced STG.32.
        const size_t ob = (((size_t)n * INH + ihh) * INW) * CIN;
#pragma unroll
        for (int e = 0; e < 16; ++e) {         // 4096 half2
            int flat = e * 256 + tid;
            int iw = flat >> 6, ci2 = flat & 63;
            __half2 h = __floats2half2_rn(tile[2 * ci2][iw], tile[2 * ci2 + 1][iw]);
            *reinterpret_cast<__half2*>(g_xh + ob + (size_t)iw * CIN + 2 * ci2) = h;
        }
    } else {
        const int base = (bid - 2048) * 2048;  // 128 blocks x 2048 elems
#pragma unroll
        for (int e = 0; e < 8; ++e) {
            const int idx = base + e * 256 + tid;   // < 262144
            const int k = idx & 511;
            const int rco = idx >> 9;
            const int co = rco & 127, par = rco >> 7;
            const int t = k >> 7, ci = k & 127;
            const int dh = t >> 1, dw = t & 1, ph = par >> 1, pw = par & 1;
            const int kh = ph + 2 * dh, kw = pw + 2 * dw;
            g_bext[idx] = __float2half_rn(W[(((size_t)(kh * 4 + kw)) * CIN + ci) * COUT + co]);
        }
    }
}

// =================== kernel 2: mma.sync GEMM (R8, unchanged) ===================
// Block = (parity, n, itile). M=128 (2 i-rows x 64 j), N=128 co.
// K' = 512, 8 chunks of 64 (tap t=c>>1, ci-half h=c&1).
// 4 warps (128 thr), 2x2 grid of 64x64 warp tiles: 4(mt) x 8(nt) m16n8k16 each.
// 3-stage cp.async pipeline, ONE barrier per chunk.
__global__ __launch_bounds__(128, 2) void tconv_gemm(const float* __restrict__ bias,
                                                     float* __restrict__ out) {
    extern __shared__ char dynsmem[];
    const uint32_t tiles = (smem_u32(dynsmem) + 1023u) & ~1023u;  // 3 x 32KB stages

    const int tid = threadIdx.x, wid = tid >> 5, lane = tid & 31;
    const int blk = blockIdx.x;
    const int par = blk & 3, rest = blk >> 2;
    const int itile = rest & 31, n = rest >> 5;
    const int ph = par >> 1, pw = par & 1;
    const int warp_m = wid >> 1, warp_n = wid & 1;    // 2x2, 64x64 per warp

    float acc[4][8][4];
#pragma unroll
    for (int mt = 0; mt < 4; ++mt)
#pragma unroll
        for (int nt = 0; nt < 8; ++nt)
#pragma unroll
            for (int q = 0; q < 4; ++q) acc[mt][nt][q] = 0.f;

    auto issue = [&](int c) {
        const int t = c >> 1, h = c & 1;
        const int dh = t >> 1, dw = t & 1;
        const uint32_t abase = tiles + (uint32_t)(c % 3) * 32768u;
        const uint32_t bbase = abase + 16384u;
        const int ih_off = itile * 2 + ph - 1 + dh;
        const int iw_off = pw - 1 + dw;
        const int kb = c * 64;
#pragma unroll
        for (int e = 0; e < 16; ++e) {
            const int idx = e * 128 + tid;
            const int row = (idx >> 3) & 127, s16 = idx & 7;
            uint32_t so = (uint32_t)(row * 128 + s16 * 16);
            so ^= (so >> 3) & 0x70;                       // SW128 swizzle
            if (idx < 1024) {                             // A: 128 m-rows x 64 k
                const int i_loc = row >> 6, j = row & 63;
                const unsigned ihx = (unsigned)(ih_off + i_loc);
                const unsigned iwx = (unsigned)(iw_off + j);
                const bool ok = (ihx < 64u) & (iwx < 64u);
                const __half* src = ok
                    ? g_xh + (((size_t)n * INH + ihx) * INW + iwx) * CIN + h * 64 + s16 * 8
                    : g_xh;                               // valid dummy, sz=0 zero-fills
                cp_async16(abase + so, src, ok ? 16u : 0u);
            } else {                                      // B: 128 co-rows x 64 k
                const __half* src =
                    g_bext + ((size_t)(par * COUT + row)) * 512 + kb + s16 * 8;
                cp_async16(bbase + so, src, 16u);
            }
        }
        CP_COMMIT();
    };

    auto compute = [&](int c) {
        const uint32_t abase = tiles + (uint32_t)(c % 3) * 32768u;
        const uint32_t bbase = abase + 16384u;
        const int arow = warp_m * 64 + (lane & 15);       // + mt*16
        const int acp0 = lane >> 4;                       // + 2*s
        const int bmtx = lane >> 3, brlo = lane & 7;
        const int brow0 = warp_n * 64 + ((bmtx >> 1) << 3) + brlo;   // + q*16
        const int bcp0 = bmtx & 1;                        // + 2*s
#pragma unroll
        for (int s = 0; s < 4; ++s) {
            uint32_t a[4][4];
#pragma unroll
            for (int mt = 0; mt < 4; ++mt) {
                const int r = arow + mt * 16;
                const uint32_t chunk = (uint32_t)((acp0 + 2 * s) ^ (r & 7));
                ldsm_x4(a[mt], abase + (uint32_t)r * 128u + chunk * 16u);
            }
            uint32_t b[4][4];                             // q -> {b0n0,b1n0,b0n1,b1n1}
#pragma unroll
            for (int q = 0; q < 4; ++q) {
                const int r = brow0 + q * 16;
                const uint32_t chunk = (uint32_t)((bcp0 + 2 * s) ^ (r & 7));
                ldsm_x4(b[q], bbase + (uint32_t)r * 128u + chunk * 16u);
            }
#pragma unroll
            for (int mt = 0; mt < 4; ++mt)
#pragma unroll
                for (int nt = 0; nt < 8; ++nt)
                    mma_fp16(acc[mt][nt], a[mt], &b[nt >> 1][(nt & 1) * 2]);
        }
    };

    issue(0);
    issue(1);
#pragma unroll 1
    for (int c = 0; c < 8; ++c) {
        if (c < 7) { CP_WAIT(1); } else { CP_WAIT(0); }
        __syncthreads();
        compute(c);
        if (c + 2 < 8) issue(c + 2);
    }

    // ---- epilogue: registers -> gmem ----
    const int g = lane >> 2, tg = lane & 3;
    const int oh0 = 2 * (itile * 2 + warp_m) + ph;
    float* const ob = out + (size_t)n * COUT * OUTHW + (size_t)oh0 * 128 + pw;
#pragma unroll
    for (int nt = 0; nt < 8; ++nt) {
        const int co = warp_n * 64 + nt * 8 + 2 * tg;
        const float b0 = __ldg(&bias[co]), b1 = __ldg(&bias[co + 1]);
        float* const oc0 = ob + (size_t)co * OUTHW;
        float* const oc1 = oc0 + OUTHW;
#pragma unroll
        for (int mt = 0; mt < 4; ++mt) {
            const int j0 = mt * 16 + g;
            oc0[2 * j0]        = acc[mt][nt][0] + b0;
            oc1[2 * j0]        = acc[mt][nt][1] + b1;
            oc0[2 * (j0 + 8)]  = acc[mt][nt][2] + b0;
            oc1[2 * (j0 + 8)]  = acc[mt][nt][3] + b1;
        }
    }
}

// =================== launch ===================
extern "C" void kernel_launch(void* const* d_in, const int* in_sizes, int n_in,
                              void* d_out, int out_size) {
    const float* x = (const float*)d_in[0];
    const float* W = (const float*)d_in[1];
    const float* b = (const float*)d_in[2];
    float* out = (float*)d_out;

    const int SMEM_DYN = 3 * 32768 + 1024;   // 3 stages + align pad
    cudaFuncSetAttribute(tconv_gemm, cudaFuncAttributeMaxDynamicSharedMemorySize, SMEM_DYN);

    prologue_kernel<<<2176, 256>>>(x, W);            // 2048 convert + 128 bext blocks
    tconv_gemm<<<4096, 128, SMEM_DYN>>>(b, out);     // (n*32+itile)*4 + parity
}